// round 11
// baseline (speedup 1.0000x reference)
#include <cuda_runtime.h>
#include <cuda_fp16.h>
#include <cstdint>

// Problem constants
static constexpr int O_DIM = 4096;     // out features (N)
static constexpr int I_DIM = 4096;     // in features (K)
static constexpr int M_DIM = 8 * 2048; // batch*seq (M)
static constexpr int R_DIM = 16;       // LoRA rank

// Scratch: fp16 operands (device globals — no allocation allowed)
__device__ __align__(16) __half g_Wq[(size_t)O_DIM * I_DIM];
__device__ __align__(16) __half g_Xq[(size_t)M_DIM * I_DIM];

// ---------------------------------------------------------------------------
// Fused prep kernel (round-8, kept).
// ---------------------------------------------------------------------------
static constexpr int XPT = 2;  // float4 elements per thread in x path
static constexpr int XBLK =
    (int)(((size_t)M_DIM * I_DIM / 4) / (256 * XPT));   // 32768 blocks

__global__ void prep_fused(const int* __restrict__ qw,
                           const float* __restrict__ scales,
                           const float* __restrict__ up,
                           const float* __restrict__ down,
                           const float* __restrict__ x) {
    const int tid = threadIdx.x;
    if (blockIdx.x < O_DIM) {
        const int o = blockIdx.x;
        __shared__ float up_s[R_DIM];
        if (tid < R_DIM) up_s[tid] = up[o * R_DIM + tid];
        __syncthreads();

        const int4* qrow = (const int4*)(qw + (size_t)o * I_DIM);
        for (int i = tid; i < I_DIM / 4; i += blockDim.x) {
            const int4 q = qrow[i];
            const float sc = scales[o * (I_DIM / 32) + (i >> 3)];
            float l[4] = {0.f, 0.f, 0.f, 0.f};
#pragma unroll
            for (int r = 0; r < R_DIM; r++) {
                const float4 d4 = ((const float4*)(down + (size_t)r * I_DIM))[i];
                const float u = up_s[r];
                l[0] = fmaf(u, d4.x, l[0]); l[1] = fmaf(u, d4.y, l[1]);
                l[2] = fmaf(u, d4.z, l[2]); l[3] = fmaf(u, d4.w, l[3]);
            }
            float w[4];
            w[0] = fmaf(sc, (float)q.x - 128.f, 0.5f * l[0]);
            w[1] = fmaf(sc, (float)q.y - 128.f, 0.5f * l[1]);
            w[2] = fmaf(sc, (float)q.z - 128.f, 0.5f * l[2]);
            w[3] = fmaf(sc, (float)q.w - 128.f, 0.5f * l[3]);
            union { __half h[4]; uint2 u; } P;
#pragma unroll
            for (int j = 0; j < 4; j++) P.h[j] = __float2half_rn(w[j]);
            ((uint2*)g_Wq)[(size_t)o * (I_DIM / 4) + i] = P.u;
        }
    } else {
        const size_t t = (size_t)(blockIdx.x - O_DIM) * blockDim.x + tid;
        const size_t i4 = t * XPT;
        const float4 v0 = ((const float4*)x)[i4];
        const float4 v1 = ((const float4*)x)[i4 + 1];
        union { __half h[8]; uint4 u; } P;
        P.h[0] = __float2half_rn(v0.x); P.h[1] = __float2half_rn(v0.y);
        P.h[2] = __float2half_rn(v0.z); P.h[3] = __float2half_rn(v0.w);
        P.h[4] = __float2half_rn(v1.x); P.h[5] = __float2half_rn(v1.y);
        P.h[6] = __float2half_rn(v1.z); P.h[7] = __float2half_rn(v1.w);
        __stcs((uint4*)g_Xq + t, P.u);
    }
}

// ---------------------------------------------------------------------------
// GEMM  out[M][N] = Xq @ Wq^T + bias
// 128x128 block tile, BK=64 as two proven 32-k subtiles, 4 warps (64x64 warp
// tile), 3-stage cp.async pipeline (wait_group 1, one barrier per 64-k tile).
// ---------------------------------------------------------------------------
static constexpr int BM = 128, BN = 128, BK = 64;
static constexpr int KT = I_DIM / BK;          // 64 K-tiles
static constexpr int NS = 3;                   // pipeline stages
static constexpr int SUB_BYTES = BM * 64;      // 8192 B per 32-k subtile buffer
static constexpr int STAGE_BYTES = 4 * SUB_BYTES;    // A0,A1,B0,B1 = 32768
static constexpr int SMEM_BYTES = NS * STAGE_BYTES;  // 98304
static constexpr int OFF_A = 0;                // A0 at 0, A1 at SUB_BYTES
static constexpr int OFF_B = 2 * SUB_BYTES;    // B0, B1
static constexpr int NTHREADS = 128;

__device__ __forceinline__ uint32_t cvta_smem(const void* p) {
    return (uint32_t)__cvta_generic_to_shared(p);
}
__device__ __forceinline__ void cp_async16(uint32_t s, const void* g) {
    asm volatile("cp.async.cg.shared.global [%0], [%1], 16;" :: "r"(s), "l"(g));
}
__device__ __forceinline__ void ldsm4(uint32_t (&r)[4], uint32_t addr) {
    asm volatile("ldmatrix.sync.aligned.m8n8.x4.shared.b16 {%0,%1,%2,%3}, [%4];"
                 : "=r"(r[0]), "=r"(r[1]), "=r"(r[2]), "=r"(r[3]) : "r"(addr));
}
__device__ __forceinline__ void mma16816(float (&d)[4], const uint32_t (&a)[4],
                                         uint32_t b0, uint32_t b1) {
    asm volatile(
        "mma.sync.aligned.m16n8k16.row.col.f32.f16.f16.f32 "
        "{%0,%1,%2,%3}, {%4,%5,%6,%7}, {%8,%9}, {%0,%1,%2,%3};"
        : "+f"(d[0]), "+f"(d[1]), "+f"(d[2]), "+f"(d[3])
        : "r"(a[0]), "r"(a[1]), "r"(a[2]), "r"(a[3]), "r"(b0), "r"(b1));
}

// Swizzle: 16B chunk c (0..3) in 64B row -> physical chunk c ^ ((row>>1)&3).
__device__ __forceinline__ uint32_t swz(int row, int c) {
    return (uint32_t)(row * 64 + ((c ^ ((row >> 1) & 3)) << 4));
}

__global__ __launch_bounds__(NTHREADS, 2)
void gemm_fp16(const float* __restrict__ bias, float* __restrict__ out) {
    extern __shared__ __align__(16) uint8_t smem[];
    const int tid  = threadIdx.x;
    const int lane = tid & 31;
    const int warp = tid >> 5;
    const int wm = warp >> 1;   // 0..1 (M)
    const int wn = warp & 1;    // 0..1 (N)
    const int m0 = blockIdx.y * BM;
    const int n0 = blockIdx.x * BN;

    const __half* aQ = g_Xq + (size_t)m0 * I_DIM;
    const __half* bQ = g_Wq + (size_t)n0 * I_DIM;

    const uint32_t sbase = cvta_smem(smem);

    // Loader geometry: per 8KB subtile, 512 chunks / 128 threads = 4 rows each.
    const int ldRow = tid >> 2;   // 0..31
    const int ldC   = tid & 3;
    uint32_t so[4];
    size_t gofs[4];
#pragma unroll
    for (int j = 0; j < 4; j++) {
        so[j] = swz(ldRow + 32 * j, ldC);
        gofs[j] = (size_t)(ldRow + 32 * j) * I_DIM + ldC * 8;
    }

    // Loop-invariant ldsm offsets (within a 32-k subtile; ksh = k-half 0/1)
    uint32_t aoff[2][4], boff[2][4];
#pragma unroll
    for (int ksh = 0; ksh < 2; ksh++) {
#pragma unroll
        for (int mt = 0; mt < 4; mt++)
            aoff[ksh][mt] = swz(wm * 64 + mt * 16 + (lane & 15),
                                ksh * 2 + (lane >> 4));
#pragma unroll
        for (int np = 0; np < 4; np++)
            boff[ksh][np] = swz(wn * 64 + np * 16 + (lane & 7) + ((lane >> 4) << 3),
                                ksh * 2 + ((lane >> 3) & 1));
    }

    float acc[4][8][4];
#pragma unroll
    for (int a = 0; a < 4; a++)
#pragma unroll
        for (int b = 0; b < 8; b++)
#pragma unroll
            for (int c = 0; c < 4; c++) acc[a][b][c] = 0.f;

#define LOAD_STAGE(T) do {                                                    \
        const uint32_t sb = sbase + ((T) % NS) * STAGE_BYTES;                 \
        const size_t k0 = (size_t)(T) * BK;                                   \
        _Pragma("unroll")                                                     \
        for (int sub = 0; sub < 2; sub++) {                                   \
            _Pragma("unroll")                                                 \
            for (int j = 0; j < 4; j++) {                                     \
                cp_async16(sb + OFF_A + sub * SUB_BYTES + so[j],              \
                           aQ + gofs[j] + k0 + sub * 32);                     \
                cp_async16(sb + OFF_B + sub * SUB_BYTES + so[j],              \
                           bQ + gofs[j] + k0 + sub * 32);                     \
            }                                                                 \
        }                                                                     \
        asm volatile("cp.async.commit_group;");                               \
    } while (0)

    // Prologue: stages 0..NS-2
#pragma unroll
    for (int t = 0; t < NS - 1; t++) LOAD_STAGE(t);

    for (int kt = 0; kt < KT; kt++) {
        asm volatile("cp.async.wait_group %0;" :: "n"(NS - 2));
        __syncthreads();   // stage kt ready; all warps done with stage kt-1
        if (kt + NS - 1 < KT) {
            LOAD_STAGE(kt + NS - 1);
        } else {
            asm volatile("cp.async.commit_group;");
        }

        const uint32_t sb = sbase + (kt % NS) * STAGE_BYTES;

#pragma unroll
        for (int ks = 0; ks < 4; ks++) {
            const int sub = ks >> 1, ksh = ks & 1;
            const uint32_t aB = sb + OFF_A + sub * SUB_BYTES;
            const uint32_t bB = sb + OFF_B + sub * SUB_BYTES;
            uint32_t af[4][4];
#pragma unroll
            for (int mt = 0; mt < 4; mt++) ldsm4(af[mt], aB + aoff[ksh][mt]);
#pragma unroll
            for (int np = 0; np < 4; np++) {
                uint32_t bf[4];
                ldsm4(bf, bB + boff[ksh][np]);
#pragma unroll
                for (int mt = 0; mt < 4; mt++) {
                    mma16816(acc[mt][np * 2 + 0], af[mt], bf[0], bf[1]);
                    mma16816(acc[mt][np * 2 + 1], af[mt], bf[2], bf[3]);
                }
            }
        }
    }
#undef LOAD_STAGE

    // Epilogue: + bias, fp32 out, streaming float2 stores
#pragma unroll
    for (int mt = 0; mt < 4; mt++) {
#pragma unroll
        for (int nt = 0; nt < 8; nt++) {
            const int row = m0 + wm * 64 + mt * 16 + (lane >> 2);
            const int col = n0 + wn * 64 + nt * 8 + (lane & 3) * 2;
            const float b0 = bias[col], b1 = bias[col + 1];
            float2 v0 = {acc[mt][nt][0] + b0, acc[mt][nt][1] + b1};
            float2 v1 = {acc[mt][nt][2] + b0, acc[mt][nt][3] + b1};
            __stcs((float2*)(out + (size_t)row * O_DIM + col), v0);
            __stcs((float2*)(out + (size_t)(row + 8) * O_DIM + col), v1);
        }
    }
}

// ---------------------------------------------------------------------------
extern "C" void kernel_launch(void* const* d_in, const int* in_sizes, int n_in,
                              void* d_out, int out_size) {
    const int*   qweight   = (const int*)d_in[0];
    const float* scales    = (const float*)d_in[1];
    const float* lora_up   = (const float*)d_in[2];
    const float* lora_down = (const float*)d_in[3];
    const float* bias      = (const float*)d_in[4];
    const float* x         = (const float*)d_in[5];
    float* out = (float*)d_out;

    prep_fused<<<O_DIM + XBLK, 256>>>(qweight, scales, lora_up, lora_down, x);

    cudaFuncSetAttribute(gemm_fp16,
                         cudaFuncAttributeMaxDynamicSharedMemorySize, SMEM_BYTES);
    dim3 grid(O_DIM / BN, M_DIM / BM);  // (32, 128)
    gemm_fp16<<<grid, NTHREADS, SMEM_BYTES>>>(bias, out);
}

// round 12
// speedup vs baseline: 1.0966x; 1.0966x over previous
#include <cuda_runtime.h>
#include <cuda_fp16.h>
#include <cstdint>

// Problem constants
static constexpr int O_DIM = 4096;     // out features (N)
static constexpr int I_DIM = 4096;     // in features (K)
static constexpr int M_DIM = 8 * 2048; // batch*seq (M)
static constexpr int R_DIM = 16;       // LoRA rank

// Scratch: fp16 operands (device globals — no allocation allowed)
__device__ __align__(16) __half g_Wq[(size_t)O_DIM * I_DIM];
__device__ __align__(16) __half g_Xq[(size_t)M_DIM * I_DIM];

// ---------------------------------------------------------------------------
// Fused prep kernel (round-8, kept).
// ---------------------------------------------------------------------------
static constexpr int XPT = 2;  // float4 elements per thread in x path
static constexpr int XBLK =
    (int)(((size_t)M_DIM * I_DIM / 4) / (256 * XPT));   // 32768 blocks

__global__ void prep_fused(const int* __restrict__ qw,
                           const float* __restrict__ scales,
                           const float* __restrict__ up,
                           const float* __restrict__ down,
                           const float* __restrict__ x) {
    const int tid = threadIdx.x;
    if (blockIdx.x < O_DIM) {
        const int o = blockIdx.x;
        __shared__ float up_s[R_DIM];
        if (tid < R_DIM) up_s[tid] = up[o * R_DIM + tid];
        __syncthreads();

        const int4* qrow = (const int4*)(qw + (size_t)o * I_DIM);
        for (int i = tid; i < I_DIM / 4; i += blockDim.x) {
            const int4 q = qrow[i];
            const float sc = scales[o * (I_DIM / 32) + (i >> 3)];
            float l[4] = {0.f, 0.f, 0.f, 0.f};
#pragma unroll
            for (int r = 0; r < R_DIM; r++) {
                const float4 d4 = ((const float4*)(down + (size_t)r * I_DIM))[i];
                const float u = up_s[r];
                l[0] = fmaf(u, d4.x, l[0]); l[1] = fmaf(u, d4.y, l[1]);
                l[2] = fmaf(u, d4.z, l[2]); l[3] = fmaf(u, d4.w, l[3]);
            }
            float w[4];
            w[0] = fmaf(sc, (float)q.x - 128.f, 0.5f * l[0]);
            w[1] = fmaf(sc, (float)q.y - 128.f, 0.5f * l[1]);
            w[2] = fmaf(sc, (float)q.z - 128.f, 0.5f * l[2]);
            w[3] = fmaf(sc, (float)q.w - 128.f, 0.5f * l[3]);
            union { __half h[4]; uint2 u; } P;
#pragma unroll
            for (int j = 0; j < 4; j++) P.h[j] = __float2half_rn(w[j]);
            ((uint2*)g_Wq)[(size_t)o * (I_DIM / 4) + i] = P.u;
        }
    } else {
        const size_t t = (size_t)(blockIdx.x - O_DIM) * blockDim.x + tid;
        const size_t i4 = t * XPT;
        const float4 v0 = ((const float4*)x)[i4];
        const float4 v1 = ((const float4*)x)[i4 + 1];
        union { __half h[8]; uint4 u; } P;
        P.h[0] = __float2half_rn(v0.x); P.h[1] = __float2half_rn(v0.y);
        P.h[2] = __float2half_rn(v0.z); P.h[3] = __float2half_rn(v0.w);
        P.h[4] = __float2half_rn(v1.x); P.h[5] = __float2half_rn(v1.y);
        P.h[6] = __float2half_rn(v1.z); P.h[7] = __float2half_rn(v1.w);
        __stcs((uint4*)g_Xq + t, P.u);
    }
}

// ---------------------------------------------------------------------------
// GEMM  out[M][N] = Xq @ Wq^T + bias
// R9-proven mainloop: 128x128x32 tile, 4 warps (64x64 warp tile), 4-stage
// cp.async pipeline (wait_group 2, one barrier/K-tile). This round: 3 CTAs/SM
// via __launch_bounds__(128,3) — regs squeezed to 170, 12 warps/SM.
// ---------------------------------------------------------------------------
static constexpr int BM = 128, BN = 128, BK = 32;
static constexpr int KT = I_DIM / BK;          // 128 K-tiles
static constexpr int NS = 4;                   // pipeline stages
static constexpr int TILE_BYTES = BM * 64;     // 8192 B per buffer (row = 64B)
static constexpr int STAGE_BYTES = 2 * TILE_BYTES;   // A, B
static constexpr int SMEM_BYTES = NS * STAGE_BYTES;  // 65536
static constexpr int NTHREADS = 128;

__device__ __forceinline__ uint32_t cvta_smem(const void* p) {
    return (uint32_t)__cvta_generic_to_shared(p);
}
__device__ __forceinline__ void cp_async16(uint32_t s, const void* g) {
    asm volatile("cp.async.cg.shared.global [%0], [%1], 16;" :: "r"(s), "l"(g));
}
__device__ __forceinline__ void ldsm4(uint32_t (&r)[4], uint32_t addr) {
    asm volatile("ldmatrix.sync.aligned.m8n8.x4.shared.b16 {%0,%1,%2,%3}, [%4];"
                 : "=r"(r[0]), "=r"(r[1]), "=r"(r[2]), "=r"(r[3]) : "r"(addr));
}
__device__ __forceinline__ void mma16816(float (&d)[4], const uint32_t (&a)[4],
                                         uint32_t b0, uint32_t b1) {
    asm volatile(
        "mma.sync.aligned.m16n8k16.row.col.f32.f16.f16.f32 "
        "{%0,%1,%2,%3}, {%4,%5,%6,%7}, {%8,%9}, {%0,%1,%2,%3};"
        : "+f"(d[0]), "+f"(d[1]), "+f"(d[2]), "+f"(d[3])
        : "r"(a[0]), "r"(a[1]), "r"(a[2]), "r"(a[3]), "r"(b0), "r"(b1));
}

// Swizzle: 16B chunk c (0..3) in 64B row -> physical chunk c ^ ((row>>1)&3).
__device__ __forceinline__ uint32_t swz(int row, int c) {
    return (uint32_t)(row * 64 + ((c ^ ((row >> 1) & 3)) << 4));
}

__global__ __launch_bounds__(NTHREADS, 3)
void gemm_fp16(const float* __restrict__ bias, float* __restrict__ out) {
    extern __shared__ __align__(16) uint8_t smem[];
    const int tid  = threadIdx.x;
    const int lane = tid & 31;
    const int warp = tid >> 5;
    const int wm = warp >> 1;   // 0..1 (M)
    const int wn = warp & 1;    // 0..1 (N)
    const int m0 = blockIdx.y * BM;
    const int n0 = blockIdx.x * BN;

    const __half* aQ = g_Xq + (size_t)m0 * I_DIM;
    const __half* bQ = g_Wq + (size_t)n0 * I_DIM;

    const uint32_t sbase = cvta_smem(smem);

    // Loader geometry: 512 16B-chunks per buffer / 128 threads = 4 rows each.
    // 32-bit element offsets (buffers < 2^31 elements) to save registers.
    const int ldRow = tid >> 2;   // 0..31
    const int ldC   = tid & 3;
    uint32_t so[4];
    uint32_t gofs[4];
#pragma unroll
    for (int j = 0; j < 4; j++) {
        so[j] = swz(ldRow + 32 * j, ldC);
        gofs[j] = (uint32_t)(ldRow + 32 * j) * I_DIM + ldC * 8;
    }

    // Loop-invariant ldsm offsets (warp tile 64x64)
    uint32_t aoff[2][4], boff[2][4];
#pragma unroll
    for (int ks = 0; ks < 2; ks++) {
#pragma unroll
        for (int mt = 0; mt < 4; mt++)
            aoff[ks][mt] = swz(wm * 64 + mt * 16 + (lane & 15),
                               ks * 2 + (lane >> 4));
#pragma unroll
        for (int np = 0; np < 4; np++)
            boff[ks][np] = swz(wn * 64 + np * 16 + (lane & 7) + ((lane >> 4) << 3),
                               ks * 2 + ((lane >> 3) & 1));
    }

    float acc[4][8][4];
#pragma unroll
    for (int a = 0; a < 4; a++)
#pragma unroll
        for (int b = 0; b < 8; b++)
#pragma unroll
            for (int c = 0; c < 4; c++) acc[a][b][c] = 0.f;

#define LOAD_STAGE(T) do {                                                    \
        const uint32_t sb = sbase + ((T) & (NS - 1)) * STAGE_BYTES;           \
        const uint32_t k0 = (uint32_t)(T) * BK;                               \
        _Pragma("unroll")                                                     \
        for (int j = 0; j < 4; j++) {                                         \
            cp_async16(sb + 0 * TILE_BYTES + so[j], aQ + gofs[j] + k0);       \
            cp_async16(sb + 1 * TILE_BYTES + so[j], bQ + gofs[j] + k0);       \
        }                                                                     \
        asm volatile("cp.async.commit_group;");                               \
    } while (0)

    // Prologue: stages 0..NS-2
#pragma unroll
    for (int t = 0; t < NS - 1; t++) LOAD_STAGE(t);

    for (int kt = 0; kt < KT; kt++) {
        asm volatile("cp.async.wait_group %0;" :: "n"(NS - 2));
        __syncthreads();
        if (kt + NS - 1 < KT) {
            LOAD_STAGE(kt + NS - 1);
        } else {
            asm volatile("cp.async.commit_group;");
        }

        const uint32_t sb = sbase + (kt & (NS - 1)) * STAGE_BYTES;
        const uint32_t aB = sb + 0 * TILE_BYTES;
        const uint32_t bB = sb + 1 * TILE_BYTES;

#pragma unroll
        for (int ks = 0; ks < 2; ks++) {
            uint32_t af[4][4];
#pragma unroll
            for (int mt = 0; mt < 4; mt++) ldsm4(af[mt], aB + aoff[ks][mt]);
#pragma unroll
            for (int np = 0; np < 4; np++) {
                uint32_t bf[4];
                ldsm4(bf, bB + boff[ks][np]);
#pragma unroll
                for (int mt = 0; mt < 4; mt++) {
                    mma16816(acc[mt][np * 2 + 0], af[mt], bf[0], bf[1]);
                    mma16816(acc[mt][np * 2 + 1], af[mt], bf[2], bf[3]);
                }
            }
        }
    }
#undef LOAD_STAGE

    // Epilogue: + bias, fp32 out, streaming float2 stores
#pragma unroll
    for (int mt = 0; mt < 4; mt++) {
#pragma unroll
        for (int nt = 0; nt < 8; nt++) {
            const int row = m0 + wm * 64 + mt * 16 + (lane >> 2);
            const int col = n0 + wn * 64 + nt * 8 + (lane & 3) * 2;
            const float b0 = bias[col], b1 = bias[col + 1];
            float2 v0 = {acc[mt][nt][0] + b0, acc[mt][nt][1] + b1};
            float2 v1 = {acc[mt][nt][2] + b0, acc[mt][nt][3] + b1};
            __stcs((float2*)(out + (size_t)row * O_DIM + col), v0);
            __stcs((float2*)(out + (size_t)(row + 8) * O_DIM + col), v1);
        }
    }
}

// ---------------------------------------------------------------------------
extern "C" void kernel_launch(void* const* d_in, const int* in_sizes, int n_in,
                              void* d_out, int out_size) {
    const int*   qweight   = (const int*)d_in[0];
    const float* scales    = (const float*)d_in[1];
    const float* lora_up   = (const float*)d_in[2];
    const float* lora_down = (const float*)d_in[3];
    const float* bias      = (const float*)d_in[4];
    const float* x         = (const float*)d_in[5];
    float* out = (float*)d_out;

    prep_fused<<<O_DIM + XBLK, 256>>>(qweight, scales, lora_up, lora_down, x);

    cudaFuncSetAttribute(gemm_fp16,
                         cudaFuncAttributeMaxDynamicSharedMemorySize, SMEM_BYTES);
    dim3 grid(O_DIM / BN, M_DIM / BM);  // (32, 128)
    gemm_fp16<<<grid, NTHREADS, SMEM_BYTES>>>(bias, out);
}

// round 13
// speedup vs baseline: 1.2215x; 1.1139x over previous
#include <cuda_runtime.h>
#include <cuda_fp16.h>
#include <cstdint>

// Problem constants
static constexpr int O_DIM = 4096;     // out features (N)
static constexpr int I_DIM = 4096;     // in features (K)
static constexpr int M_DIM = 8 * 2048; // batch*seq (M)
static constexpr int R_DIM = 16;       // LoRA rank

// Scratch: fp16 operands (device globals — no allocation allowed)
__device__ __align__(16) __half g_Wq[(size_t)O_DIM * I_DIM];
__device__ __align__(16) __half g_Xq[(size_t)M_DIM * I_DIM];

// ---------------------------------------------------------------------------
// Fused prep kernel. W path unchanged; X path widened to 4 float4 per thread.
// ---------------------------------------------------------------------------
static constexpr int XPT = 4;  // float4 elements per thread in x path
static constexpr int XBLK =
    (int)(((size_t)M_DIM * I_DIM / 4) / (256 * XPT));   // 16384 blocks

__global__ void prep_fused(const int* __restrict__ qw,
                           const float* __restrict__ scales,
                           const float* __restrict__ up,
                           const float* __restrict__ down,
                           const float* __restrict__ x) {
    const int tid = threadIdx.x;
    if (blockIdx.x < O_DIM) {
        const int o = blockIdx.x;
        __shared__ float up_s[R_DIM];
        if (tid < R_DIM) up_s[tid] = up[o * R_DIM + tid];
        __syncthreads();

        const int4* qrow = (const int4*)(qw + (size_t)o * I_DIM);
        for (int i = tid; i < I_DIM / 4; i += blockDim.x) {
            const int4 q = qrow[i];
            const float sc = scales[o * (I_DIM / 32) + (i >> 3)];
            float l[4] = {0.f, 0.f, 0.f, 0.f};
#pragma unroll
            for (int r = 0; r < R_DIM; r++) {
                const float4 d4 = ((const float4*)(down + (size_t)r * I_DIM))[i];
                const float u = up_s[r];
                l[0] = fmaf(u, d4.x, l[0]); l[1] = fmaf(u, d4.y, l[1]);
                l[2] = fmaf(u, d4.z, l[2]); l[3] = fmaf(u, d4.w, l[3]);
            }
            float w[4];
            w[0] = fmaf(sc, (float)q.x - 128.f, 0.5f * l[0]);
            w[1] = fmaf(sc, (float)q.y - 128.f, 0.5f * l[1]);
            w[2] = fmaf(sc, (float)q.z - 128.f, 0.5f * l[2]);
            w[3] = fmaf(sc, (float)q.w - 128.f, 0.5f * l[3]);
            union { __half h[4]; uint2 u; } P;
#pragma unroll
            for (int j = 0; j < 4; j++) P.h[j] = __float2half_rn(w[j]);
            ((uint2*)g_Wq)[(size_t)o * (I_DIM / 4) + i] = P.u;
        }
    } else {
        // X path: 4 float4 (64B) -> 2 uint4 streaming stores (32B)
        const size_t t = (size_t)(blockIdx.x - O_DIM) * blockDim.x + tid;
        const size_t i4 = t * XPT;
#pragma unroll
        for (int h = 0; h < 2; h++) {
            const float4 v0 = ((const float4*)x)[i4 + 2 * h];
            const float4 v1 = ((const float4*)x)[i4 + 2 * h + 1];
            union { __half hh[8]; uint4 u; } P;
            P.hh[0] = __float2half_rn(v0.x); P.hh[1] = __float2half_rn(v0.y);
            P.hh[2] = __float2half_rn(v0.z); P.hh[3] = __float2half_rn(v0.w);
            P.hh[4] = __float2half_rn(v1.x); P.hh[5] = __float2half_rn(v1.y);
            P.hh[6] = __float2half_rn(v1.z); P.hh[7] = __float2half_rn(v1.w);
            __stcs((uint4*)g_Xq + t * 2 + h, P.u);
        }
    }
}

// ---------------------------------------------------------------------------
// GEMM  out[M][N] = Xq @ Wq^T + bias
// EXACT round-9 mainloop (best known: 1180.7us, tensor 84%), plus a K-phase
// stagger: odd CTAs start the K sweep at KT/2 and wrap, to anti-phase the two
// co-resident CTAs' barriers/load bursts.
// ---------------------------------------------------------------------------
static constexpr int BM = 128, BN = 128, BK = 32;
static constexpr int KT = I_DIM / BK;          // 128 K-tiles
static constexpr int NS = 4;                   // pipeline stages
static constexpr int TILE_BYTES = BM * 64;     // 8192 B per buffer (row = 64B)
static constexpr int STAGE_BYTES = 2 * TILE_BYTES;   // A, B
static constexpr int SMEM_BYTES = NS * STAGE_BYTES;  // 65536
static constexpr int NTHREADS = 128;

__device__ __forceinline__ uint32_t cvta_smem(const void* p) {
    return (uint32_t)__cvta_generic_to_shared(p);
}
__device__ __forceinline__ void cp_async16(uint32_t s, const void* g) {
    asm volatile("cp.async.cg.shared.global [%0], [%1], 16;" :: "r"(s), "l"(g));
}
__device__ __forceinline__ void ldsm4(uint32_t (&r)[4], uint32_t addr) {
    asm volatile("ldmatrix.sync.aligned.m8n8.x4.shared.b16 {%0,%1,%2,%3}, [%4];"
                 : "=r"(r[0]), "=r"(r[1]), "=r"(r[2]), "=r"(r[3]) : "r"(addr));
}
__device__ __forceinline__ void mma16816(float (&d)[4], const uint32_t (&a)[4],
                                         uint32_t b0, uint32_t b1) {
    asm volatile(
        "mma.sync.aligned.m16n8k16.row.col.f32.f16.f16.f32 "
        "{%0,%1,%2,%3}, {%4,%5,%6,%7}, {%8,%9}, {%0,%1,%2,%3};"
        : "+f"(d[0]), "+f"(d[1]), "+f"(d[2]), "+f"(d[3])
        : "r"(a[0]), "r"(a[1]), "r"(a[2]), "r"(a[3]), "r"(b0), "r"(b1));
}

// Swizzle: 16B chunk c (0..3) in 64B row -> physical chunk c ^ ((row>>1)&3).
__device__ __forceinline__ uint32_t swz(int row, int c) {
    return (uint32_t)(row * 64 + ((c ^ ((row >> 1) & 3)) << 4));
}

__global__ __launch_bounds__(NTHREADS, 2)
void gemm_fp16(const float* __restrict__ bias, float* __restrict__ out) {
    extern __shared__ __align__(16) uint8_t smem[];
    const int tid  = threadIdx.x;
    const int lane = tid & 31;
    const int warp = tid >> 5;
    const int wm = warp >> 1;   // 0..1 (M)
    const int wn = warp & 1;    // 0..1 (N)
    const int m0 = blockIdx.y * BM;
    const int n0 = blockIdx.x * BN;
    // K-phase stagger: odd CTAs sweep K starting at KT/2 (wraps; fp32 sum
    // order changes, value set identical).
    const int kphase = ((blockIdx.x ^ blockIdx.y) & 1) * (KT / 2);

    const __half* aQ = g_Xq + (size_t)m0 * I_DIM;
    const __half* bQ = g_Wq + (size_t)n0 * I_DIM;

    const uint32_t sbase = cvta_smem(smem);

    // Loader geometry: 512 16B-chunks per buffer / 128 threads = 4 rows each.
    const int ldRow = tid >> 2;   // 0..31
    const int ldC   = tid & 3;
    uint32_t so[4];
    size_t gofs[4];
#pragma unroll
    for (int j = 0; j < 4; j++) {
        so[j] = swz(ldRow + 32 * j, ldC);
        gofs[j] = (size_t)(ldRow + 32 * j) * I_DIM + ldC * 8;
    }

    // Loop-invariant ldsm offsets (warp tile 64x64)
    uint32_t aoff[2][4], boff[2][4];
#pragma unroll
    for (int ks = 0; ks < 2; ks++) {
#pragma unroll
        for (int mt = 0; mt < 4; mt++)
            aoff[ks][mt] = swz(wm * 64 + mt * 16 + (lane & 15),
                               ks * 2 + (lane >> 4));
#pragma unroll
        for (int np = 0; np < 4; np++)
            boff[ks][np] = swz(wn * 64 + np * 16 + (lane & 7) + ((lane >> 4) << 3),
                               ks * 2 + ((lane >> 3) & 1));
    }

    float acc[4][8][4];
#pragma unroll
    for (int a = 0; a < 4; a++)
#pragma unroll
        for (int b = 0; b < 8; b++)
#pragma unroll
            for (int c = 0; c < 4; c++) acc[a][b][c] = 0.f;

#define LOAD_STAGE(T) do {                                                    \
        const uint32_t sb = sbase + ((T) & (NS - 1)) * STAGE_BYTES;           \
        const size_t k0 = (size_t)((((T) + kphase) & (KT - 1)) * BK);         \
        _Pragma("unroll")                                                     \
        for (int j = 0; j < 4; j++) {                                         \
            cp_async16(sb + 0 * TILE_BYTES + so[j], aQ + gofs[j] + k0);       \
            cp_async16(sb + 1 * TILE_BYTES + so[j], bQ + gofs[j] + k0);       \
        }                                                                     \
        asm volatile("cp.async.commit_group;");                               \
    } while (0)

    // Prologue: stages 0..NS-2
#pragma unroll
    for (int t = 0; t < NS - 1; t++) LOAD_STAGE(t);

    for (int kt = 0; kt < KT; kt++) {
        asm volatile("cp.async.wait_group %0;" :: "n"(NS - 2));
        __syncthreads();
        if (kt + NS - 1 < KT) {
            LOAD_STAGE(kt + NS - 1);
        } else {
            asm volatile("cp.async.commit_group;");
        }

        const uint32_t sb = sbase + (kt & (NS - 1)) * STAGE_BYTES;
        const uint32_t aB = sb + 0 * TILE_BYTES;
        const uint32_t bB = sb + 1 * TILE_BYTES;

#pragma unroll
        for (int ks = 0; ks < 2; ks++) {
            uint32_t af[4][4];
#pragma unroll
            for (int mt = 0; mt < 4; mt++) ldsm4(af[mt], aB + aoff[ks][mt]);
#pragma unroll
            for (int np = 0; np < 4; np++) {
                uint32_t bf[4];
                ldsm4(bf, bB + boff[ks][np]);
#pragma unroll
                for (int mt = 0; mt < 4; mt++) {
                    mma16816(acc[mt][np * 2 + 0], af[mt], bf[0], bf[1]);
                    mma16816(acc[mt][np * 2 + 1], af[mt], bf[2], bf[3]);
                }
            }
        }
    }
#undef LOAD_STAGE

    // Epilogue: + bias, fp32 out, streaming float2 stores
#pragma unroll
    for (int mt = 0; mt < 4; mt++) {
#pragma unroll
        for (int nt = 0; nt < 8; nt++) {
            const int row = m0 + wm * 64 + mt * 16 + (lane >> 2);
            const int col = n0 + wn * 64 + nt * 8 + (lane & 3) * 2;
            const float b0 = bias[col], b1 = bias[col + 1];
            float2 v0 = {acc[mt][nt][0] + b0, acc[mt][nt][1] + b1};
            float2 v1 = {acc[mt][nt][2] + b0, acc[mt][nt][3] + b1};
            __stcs((float2*)(out + (size_t)row * O_DIM + col), v0);
            __stcs((float2*)(out + (size_t)(row + 8) * O_DIM + col), v1);
        }
    }
}

// ---------------------------------------------------------------------------
extern "C" void kernel_launch(void* const* d_in, const int* in_sizes, int n_in,
                              void* d_out, int out_size) {
    const int*   qweight   = (const int*)d_in[0];
    const float* scales    = (const float*)d_in[1];
    const float* lora_up   = (const float*)d_in[2];
    const float* lora_down = (const float*)d_in[3];
    const float* bias      = (const float*)d_in[4];
    const float* x         = (const float*)d_in[5];
    float* out = (float*)d_out;

    prep_fused<<<O_DIM + XBLK, 256>>>(qweight, scales, lora_up, lora_down, x);

    cudaFuncSetAttribute(gemm_fp16,
                         cudaFuncAttributeMaxDynamicSharedMemorySize, SMEM_BYTES);
    dim3 grid(O_DIM / BN, M_DIM / BM);  // (32, 128)
    gemm_fp16<<<grid, NTHREADS, SMEM_BYTES>>>(bias, out);
}

// round 14
// speedup vs baseline: 1.2663x; 1.0367x over previous
#include <cuda_runtime.h>
#include <cuda_fp16.h>
#include <cstdint>

// Problem constants
static constexpr int O_DIM = 4096;     // out features (N)
static constexpr int I_DIM = 4096;     // in features (K)
static constexpr int M_DIM = 8 * 2048; // batch*seq (M)
static constexpr int R_DIM = 16;       // LoRA rank

// Scratch: fp16 operands (device globals — no allocation allowed)
__device__ __align__(16) __half g_Wq[(size_t)O_DIM * I_DIM];
__device__ __align__(16) __half g_Xq[(size_t)M_DIM * I_DIM];

// ---------------------------------------------------------------------------
// Fused prep kernel. W path: per-row dequant + LoRA. X path: fp32->fp16,
// 4 float4 per thread, streaming stores.
// ---------------------------------------------------------------------------
static constexpr int XPT = 4;  // float4 elements per thread in x path
static constexpr int XBLK =
    (int)(((size_t)M_DIM * I_DIM / 4) / (256 * XPT));   // 16384 blocks

__global__ void prep_fused(const int* __restrict__ qw,
                           const float* __restrict__ scales,
                           const float* __restrict__ up,
                           const float* __restrict__ down,
                           const float* __restrict__ x) {
    const int tid = threadIdx.x;
    if (blockIdx.x < O_DIM) {
        const int o = blockIdx.x;
        __shared__ float up_s[R_DIM];
        if (tid < R_DIM) up_s[tid] = up[o * R_DIM + tid];
        __syncthreads();

        const int4* qrow = (const int4*)(qw + (size_t)o * I_DIM);
        for (int i = tid; i < I_DIM / 4; i += blockDim.x) {
            const int4 q = qrow[i];
            const float sc = scales[o * (I_DIM / 32) + (i >> 3)];
            float l[4] = {0.f, 0.f, 0.f, 0.f};
#pragma unroll
            for (int r = 0; r < R_DIM; r++) {
                const float4 d4 = ((const float4*)(down + (size_t)r * I_DIM))[i];
                const float u = up_s[r];
                l[0] = fmaf(u, d4.x, l[0]); l[1] = fmaf(u, d4.y, l[1]);
                l[2] = fmaf(u, d4.z, l[2]); l[3] = fmaf(u, d4.w, l[3]);
            }
            float w[4];
            w[0] = fmaf(sc, (float)q.x - 128.f, 0.5f * l[0]);
            w[1] = fmaf(sc, (float)q.y - 128.f, 0.5f * l[1]);
            w[2] = fmaf(sc, (float)q.z - 128.f, 0.5f * l[2]);
            w[3] = fmaf(sc, (float)q.w - 128.f, 0.5f * l[3]);
            union { __half h[4]; uint2 u; } P;
#pragma unroll
            for (int j = 0; j < 4; j++) P.h[j] = __float2half_rn(w[j]);
            ((uint2*)g_Wq)[(size_t)o * (I_DIM / 4) + i] = P.u;
        }
    } else {
        // X path: 4 float4 (64B) -> 2 uint4 streaming stores (32B)
        const size_t t = (size_t)(blockIdx.x - O_DIM) * blockDim.x + tid;
        const size_t i4 = t * XPT;
#pragma unroll
        for (int h = 0; h < 2; h++) {
            const float4 v0 = ((const float4*)x)[i4 + 2 * h];
            const float4 v1 = ((const float4*)x)[i4 + 2 * h + 1];
            union { __half hh[8]; uint4 u; } P;
            P.hh[0] = __float2half_rn(v0.x); P.hh[1] = __float2half_rn(v0.y);
            P.hh[2] = __float2half_rn(v0.z); P.hh[3] = __float2half_rn(v0.w);
            P.hh[4] = __float2half_rn(v1.x); P.hh[5] = __float2half_rn(v1.y);
            P.hh[6] = __float2half_rn(v1.z); P.hh[7] = __float2half_rn(v1.w);
            __stcs((uint4*)g_Xq + t * 2 + h, P.u);
        }
    }
}

// ---------------------------------------------------------------------------
// GEMM  out[M][N] = Xq @ Wq^T + bias
// EXACT round-9 mainloop (best known: tensor 84%): 128x128x32 tile, 4 warps
// (64x64 warp tile), 4-stage cp.async pipeline, wait_group 2, one barrier
// per K-tile, 2 CTAs/SM.
// ---------------------------------------------------------------------------
static constexpr int BM = 128, BN = 128, BK = 32;
static constexpr int KT = I_DIM / BK;          // 128 K-tiles
static constexpr int NS = 4;                   // pipeline stages
static constexpr int TILE_BYTES = BM * 64;     // 8192 B per buffer (row = 64B)
static constexpr int STAGE_BYTES = 2 * TILE_BYTES;   // A, B
static constexpr int SMEM_BYTES = NS * STAGE_BYTES;  // 65536
static constexpr int NTHREADS = 128;

__device__ __forceinline__ uint32_t cvta_smem(const void* p) {
    return (uint32_t)__cvta_generic_to_shared(p);
}
__device__ __forceinline__ void cp_async16(uint32_t s, const void* g) {
    asm volatile("cp.async.cg.shared.global [%0], [%1], 16;" :: "r"(s), "l"(g));
}
__device__ __forceinline__ void ldsm4(uint32_t (&r)[4], uint32_t addr) {
    asm volatile("ldmatrix.sync.aligned.m8n8.x4.shared.b16 {%0,%1,%2,%3}, [%4];"
                 : "=r"(r[0]), "=r"(r[1]), "=r"(r[2]), "=r"(r[3]) : "r"(addr));
}
__device__ __forceinline__ void mma16816(float (&d)[4], const uint32_t (&a)[4],
                                         uint32_t b0, uint32_t b1) {
    asm volatile(
        "mma.sync.aligned.m16n8k16.row.col.f32.f16.f16.f32 "
        "{%0,%1,%2,%3}, {%4,%5,%6,%7}, {%8,%9}, {%0,%1,%2,%3};"
        : "+f"(d[0]), "+f"(d[1]), "+f"(d[2]), "+f"(d[3])
        : "r"(a[0]), "r"(a[1]), "r"(a[2]), "r"(a[3]), "r"(b0), "r"(b1));
}

// Swizzle: 16B chunk c (0..3) in 64B row -> physical chunk c ^ ((row>>1)&3).
__device__ __forceinline__ uint32_t swz(int row, int c) {
    return (uint32_t)(row * 64 + ((c ^ ((row >> 1) & 3)) << 4));
}

__global__ __launch_bounds__(NTHREADS, 2)
void gemm_fp16(const float* __restrict__ bias, float* __restrict__ out) {
    extern __shared__ __align__(16) uint8_t smem[];
    const int tid  = threadIdx.x;
    const int lane = tid & 31;
    const int warp = tid >> 5;
    const int wm = warp >> 1;   // 0..1 (M)
    const int wn = warp & 1;    // 0..1 (N)
    const int m0 = blockIdx.y * BM;
    const int n0 = blockIdx.x * BN;

    const __half* aQ = g_Xq + (size_t)m0 * I_DIM;
    const __half* bQ = g_Wq + (size_t)n0 * I_DIM;

    const uint32_t sbase = cvta_smem(smem);

    // Loader geometry: 512 16B-chunks per buffer / 128 threads = 4 rows each.
    const int ldRow = tid >> 2;   // 0..31
    const int ldC   = tid & 3;
    uint32_t so[4];
    size_t gofs[4];
#pragma unroll
    for (int j = 0; j < 4; j++) {
        so[j] = swz(ldRow + 32 * j, ldC);
        gofs[j] = (size_t)(ldRow + 32 * j) * I_DIM + ldC * 8;
    }

    // Loop-invariant ldsm offsets (warp tile 64x64)
    uint32_t aoff[2][4], boff[2][4];
#pragma unroll
    for (int ks = 0; ks < 2; ks++) {
#pragma unroll
        for (int mt = 0; mt < 4; mt++)
            aoff[ks][mt] = swz(wm * 64 + mt * 16 + (lane & 15),
                               ks * 2 + (lane >> 4));
#pragma unroll
        for (int np = 0; np < 4; np++)
            boff[ks][np] = swz(wn * 64 + np * 16 + (lane & 7) + ((lane >> 4) << 3),
                               ks * 2 + ((lane >> 3) & 1));
    }

    float acc[4][8][4];
#pragma unroll
    for (int a = 0; a < 4; a++)
#pragma unroll
        for (int b = 0; b < 8; b++)
#pragma unroll
            for (int c = 0; c < 4; c++) acc[a][b][c] = 0.f;

#define LOAD_STAGE(T) do {                                                    \
        const uint32_t sb = sbase + ((T) & (NS - 1)) * STAGE_BYTES;           \
        const size_t k0 = (size_t)(T) * BK;                                   \
        _Pragma("unroll")                                                     \
        for (int j = 0; j < 4; j++) {                                         \
            cp_async16(sb + 0 * TILE_BYTES + so[j], aQ + gofs[j] + k0);       \
            cp_async16(sb + 1 * TILE_BYTES + so[j], bQ + gofs[j] + k0);       \
        }                                                                     \
        asm volatile("cp.async.commit_group;");                               \
    } while (0)

    // Prologue: stages 0..NS-2
#pragma unroll
    for (int t = 0; t < NS - 1; t++) LOAD_STAGE(t);

    for (int kt = 0; kt < KT; kt++) {
        asm volatile("cp.async.wait_group %0;" :: "n"(NS - 2));
        __syncthreads();
        if (kt + NS - 1 < KT) {
            LOAD_STAGE(kt + NS - 1);
        } else {
            asm volatile("cp.async.commit_group;");
        }

        const uint32_t sb = sbase + (kt & (NS - 1)) * STAGE_BYTES;
        const uint32_t aB = sb + 0 * TILE_BYTES;
        const uint32_t bB = sb + 1 * TILE_BYTES;

#pragma unroll
        for (int ks = 0; ks < 2; ks++) {
            uint32_t af[4][4];
#pragma unroll
            for (int mt = 0; mt < 4; mt++) ldsm4(af[mt], aB + aoff[ks][mt]);
#pragma unroll
            for (int np = 0; np < 4; np++) {
                uint32_t bf[4];
                ldsm4(bf, bB + boff[ks][np]);
#pragma unroll
                for (int mt = 0; mt < 4; mt++) {
                    mma16816(acc[mt][np * 2 + 0], af[mt], bf[0], bf[1]);
                    mma16816(acc[mt][np * 2 + 1], af[mt], bf[2], bf[3]);
                }
            }
        }
    }
#undef LOAD_STAGE

    // Epilogue: + bias, fp32 out, streaming float2 stores
#pragma unroll
    for (int mt = 0; mt < 4; mt++) {
#pragma unroll
        for (int nt = 0; nt < 8; nt++) {
            const int row = m0 + wm * 64 + mt * 16 + (lane >> 2);
            const int col = n0 + wn * 64 + nt * 8 + (lane & 3) * 2;
            const float b0 = bias[col], b1 = bias[col + 1];
            float2 v0 = {acc[mt][nt][0] + b0, acc[mt][nt][1] + b1};
            float2 v1 = {acc[mt][nt][2] + b0, acc[mt][nt][3] + b1};
            __stcs((float2*)(out + (size_t)row * O_DIM + col), v0);
            __stcs((float2*)(out + (size_t)(row + 8) * O_DIM + col), v1);
        }
    }
}

// ---------------------------------------------------------------------------
extern "C" void kernel_launch(void* const* d_in, const int* in_sizes, int n_in,
                              void* d_out, int out_size) {
    const int*   qweight   = (const int*)d_in[0];
    const float* scales    = (const float*)d_in[1];
    const float* lora_up   = (const float*)d_in[2];
    const float* lora_down = (const float*)d_in[3];
    const float* bias      = (const float*)d_in[4];
    const float* x         = (const float*)d_in[5];
    float* out = (float*)d_out;

    prep_fused<<<O_DIM + XBLK, 256>>>(qweight, scales, lora_up, lora_down, x);

    cudaFuncSetAttribute(gemm_fp16,
                         cudaFuncAttributeMaxDynamicSharedMemorySize, SMEM_BYTES);
    dim3 grid(O_DIM / BN, M_DIM / BM);  // (32, 128)
    gemm_fp16<<<grid, NTHREADS, SMEM_BYTES>>>(bias, out);
}

// round 15
// speedup vs baseline: 1.2972x; 1.0244x over previous
#include <cuda_runtime.h>
#include <cuda_fp16.h>
#include <cstdint>

// Problem constants
static constexpr int O_DIM = 4096;     // out features (N)
static constexpr int I_DIM = 4096;     // in features (K)
static constexpr int M_DIM = 8 * 2048; // batch*seq (M)
static constexpr int R_DIM = 16;       // LoRA rank

// Scratch: fp16 operands (device globals — no allocation allowed)
__device__ __align__(16) __half g_Wq[(size_t)O_DIM * I_DIM];
__device__ __align__(16) __half g_Xq[(size_t)M_DIM * I_DIM];

// ---------------------------------------------------------------------------
// Fused prep kernel (round-14, kept — at DRAM floor).
// ---------------------------------------------------------------------------
static constexpr int XPT = 4;  // float4 elements per thread in x path
static constexpr int XBLK =
    (int)(((size_t)M_DIM * I_DIM / 4) / (256 * XPT));   // 16384 blocks

__global__ void prep_fused(const int* __restrict__ qw,
                           const float* __restrict__ scales,
                           const float* __restrict__ up,
                           const float* __restrict__ down,
                           const float* __restrict__ x) {
    const int tid = threadIdx.x;
    if (blockIdx.x < O_DIM) {
        const int o = blockIdx.x;
        __shared__ float up_s[R_DIM];
        if (tid < R_DIM) up_s[tid] = up[o * R_DIM + tid];
        __syncthreads();

        const int4* qrow = (const int4*)(qw + (size_t)o * I_DIM);
        for (int i = tid; i < I_DIM / 4; i += blockDim.x) {
            const int4 q = qrow[i];
            const float sc = scales[o * (I_DIM / 32) + (i >> 3)];
            float l[4] = {0.f, 0.f, 0.f, 0.f};
#pragma unroll
            for (int r = 0; r < R_DIM; r++) {
                const float4 d4 = ((const float4*)(down + (size_t)r * I_DIM))[i];
                const float u = up_s[r];
                l[0] = fmaf(u, d4.x, l[0]); l[1] = fmaf(u, d4.y, l[1]);
                l[2] = fmaf(u, d4.z, l[2]); l[3] = fmaf(u, d4.w, l[3]);
            }
            float w[4];
            w[0] = fmaf(sc, (float)q.x - 128.f, 0.5f * l[0]);
            w[1] = fmaf(sc, (float)q.y - 128.f, 0.5f * l[1]);
            w[2] = fmaf(sc, (float)q.z - 128.f, 0.5f * l[2]);
            w[3] = fmaf(sc, (float)q.w - 128.f, 0.5f * l[3]);
            union { __half h[4]; uint2 u; } P;
#pragma unroll
            for (int j = 0; j < 4; j++) P.h[j] = __float2half_rn(w[j]);
            ((uint2*)g_Wq)[(size_t)o * (I_DIM / 4) + i] = P.u;
        }
    } else {
        // X path: 4 float4 (64B) -> 2 uint4 streaming stores (32B)
        const size_t t = (size_t)(blockIdx.x - O_DIM) * blockDim.x + tid;
        const size_t i4 = t * XPT;
#pragma unroll
        for (int h = 0; h < 2; h++) {
            const float4 v0 = ((const float4*)x)[i4 + 2 * h];
            const float4 v1 = ((const float4*)x)[i4 + 2 * h + 1];
            union { __half hh[8]; uint4 u; } P;
            P.hh[0] = __float2half_rn(v0.x); P.hh[1] = __float2half_rn(v0.y);
            P.hh[2] = __float2half_rn(v0.z); P.hh[3] = __float2half_rn(v0.w);
            P.hh[4] = __float2half_rn(v1.x); P.hh[5] = __float2half_rn(v1.y);
            P.hh[6] = __float2half_rn(v1.z); P.hh[7] = __float2half_rn(v1.w);
            __stcs((uint4*)g_Xq + t * 2 + h, P.u);
        }
    }
}

// ---------------------------------------------------------------------------
// GEMM  out[M][N] = Xq @ Wq^T + bias
// Persistent CTAs (2/SM), R9-proven mainloop body unchanged. Tail loads of
// tile t are the prologue of tile t+1 — the cp.async pipeline never drains,
// and the epilogue overlaps the next tile's stage fills.
// ---------------------------------------------------------------------------
static constexpr int BM = 128, BN = 128, BK = 32;
static constexpr int KT = I_DIM / BK;          // 128 K-tiles
static constexpr int NS = 4;                   // pipeline stages
static constexpr int TILE_BYTES = BM * 64;     // 8192 B per buffer (row = 64B)
static constexpr int STAGE_BYTES = 2 * TILE_BYTES;   // A, B
static constexpr int SMEM_BYTES = NS * STAGE_BYTES;  // 65536
static constexpr int NTHREADS = 128;
static constexpr int NTILES = (M_DIM / BM) * (O_DIM / BN);   // 4096
static constexpr int NGRID_X = O_DIM / BN;     // 32 (N fast within tile id)

__device__ __forceinline__ uint32_t cvta_smem(const void* p) {
    return (uint32_t)__cvta_generic_to_shared(p);
}
__device__ __forceinline__ void cp_async16(uint32_t s, const void* g) {
    asm volatile("cp.async.cg.shared.global [%0], [%1], 16;" :: "r"(s), "l"(g));
}
__device__ __forceinline__ void ldsm4(uint32_t (&r)[4], uint32_t addr) {
    asm volatile("ldmatrix.sync.aligned.m8n8.x4.shared.b16 {%0,%1,%2,%3}, [%4];"
                 : "=r"(r[0]), "=r"(r[1]), "=r"(r[2]), "=r"(r[3]) : "r"(addr));
}
__device__ __forceinline__ void mma16816(float (&d)[4], const uint32_t (&a)[4],
                                         uint32_t b0, uint32_t b1) {
    asm volatile(
        "mma.sync.aligned.m16n8k16.row.col.f32.f16.f16.f32 "
        "{%0,%1,%2,%3}, {%4,%5,%6,%7}, {%8,%9}, {%0,%1,%2,%3};"
        : "+f"(d[0]), "+f"(d[1]), "+f"(d[2]), "+f"(d[3])
        : "r"(a[0]), "r"(a[1]), "r"(a[2]), "r"(a[3]), "r"(b0), "r"(b1));
}

// Swizzle: 16B chunk c (0..3) in 64B row -> physical chunk c ^ ((row>>1)&3).
__device__ __forceinline__ uint32_t swz(int row, int c) {
    return (uint32_t)(row * 64 + ((c ^ ((row >> 1) & 3)) << 4));
}

__global__ __launch_bounds__(NTHREADS, 2)
void gemm_fp16(const float* __restrict__ bias, float* __restrict__ out) {
    extern __shared__ __align__(16) uint8_t smem[];
    const int tid  = threadIdx.x;
    const int lane = tid & 31;
    const int warp = tid >> 5;
    const int wm = warp >> 1;   // 0..1 (M)
    const int wn = warp & 1;    // 0..1 (N)

    const uint32_t sbase = cvta_smem(smem);

    // Loader geometry: 512 16B-chunks per buffer / 128 threads = 4 rows each.
    const int ldRow = tid >> 2;   // 0..31
    const int ldC   = tid & 3;
    uint32_t so[4];
    size_t gofs[4];
#pragma unroll
    for (int j = 0; j < 4; j++) {
        so[j] = swz(ldRow + 32 * j, ldC);
        gofs[j] = (size_t)(ldRow + 32 * j) * I_DIM + ldC * 8;
    }

    // Loop-invariant ldsm offsets (warp tile 64x64)
    uint32_t aoff[2][4], boff[2][4];
#pragma unroll
    for (int ks = 0; ks < 2; ks++) {
#pragma unroll
        for (int mt = 0; mt < 4; mt++)
            aoff[ks][mt] = swz(wm * 64 + mt * 16 + (lane & 15),
                               ks * 2 + (lane >> 4));
#pragma unroll
        for (int np = 0; np < 4; np++)
            boff[ks][np] = swz(wn * 64 + np * 16 + (lane & 7) + ((lane >> 4) << 3),
                               ks * 2 + ((lane >> 3) & 1));
    }

#define LOAD_ST(PA, PB, STG, K0) do {                                         \
        const uint32_t sb_ = sbase + (STG) * STAGE_BYTES;                     \
        _Pragma("unroll")                                                     \
        for (int j = 0; j < 4; j++) {                                         \
            cp_async16(sb_ + 0 * TILE_BYTES + so[j], (PA) + gofs[j] + (K0));  \
            cp_async16(sb_ + 1 * TILE_BYTES + so[j], (PB) + gofs[j] + (K0));  \
        }                                                                     \
        asm volatile("cp.async.commit_group;");                               \
    } while (0)

    int tile = blockIdx.x;
    int m0 = (tile >> 5) * BM;          // tile id: N fast (matches old grid)
    int n0 = (tile & (NGRID_X - 1)) * BN;
    const __half* aQ = g_Xq + (size_t)m0 * I_DIM;
    const __half* bQ = g_Wq + (size_t)n0 * I_DIM;

    // Prologue: stages 0..NS-2 of the first tile
#pragma unroll
    for (int t = 0; t < NS - 1; t++) LOAD_ST(aQ, bQ, t, (size_t)t * BK);

    float acc[4][8][4];

    for (;;) {
#pragma unroll
        for (int a = 0; a < 4; a++)
#pragma unroll
            for (int b = 0; b < 8; b++)
#pragma unroll
                for (int c = 0; c < 4; c++) acc[a][b][c] = 0.f;

        const int ntile = tile + (int)gridDim.x;
        const bool hasn = ntile < NTILES;
        const int mn0 = hasn ? (ntile >> 5) * BM : m0;
        const int nn0 = hasn ? (ntile & (NGRID_X - 1)) * BN : n0;
        const __half* aN = g_Xq + (size_t)mn0 * I_DIM;
        const __half* bN = g_Wq + (size_t)nn0 * I_DIM;

        for (int kt = 0; kt < KT; kt++) {
            asm volatile("cp.async.wait_group %0;" :: "n"(NS - 2));
            __syncthreads();
            const int T = kt + NS - 1;
            if (T < KT) {
                LOAD_ST(aQ, bQ, T & (NS - 1), (size_t)T * BK);
            } else if (hasn) {
                // tail: prologue of next tile, pipeline never drains
                LOAD_ST(aN, bN, T & (NS - 1), (size_t)(T - KT) * BK);
            } else {
                asm volatile("cp.async.commit_group;");
            }

            const uint32_t sb = sbase + (kt & (NS - 1)) * STAGE_BYTES;
            const uint32_t aB = sb + 0 * TILE_BYTES;
            const uint32_t bB = sb + 1 * TILE_BYTES;

#pragma unroll
            for (int ks = 0; ks < 2; ks++) {
                uint32_t af[4][4];
#pragma unroll
                for (int mt = 0; mt < 4; mt++) ldsm4(af[mt], aB + aoff[ks][mt]);
#pragma unroll
                for (int np = 0; np < 4; np++) {
                    uint32_t bf[4];
                    ldsm4(bf, bB + boff[ks][np]);
#pragma unroll
                    for (int mt = 0; mt < 4; mt++) {
                        mma16816(acc[mt][np * 2 + 0], af[mt], bf[0], bf[1]);
                        mma16816(acc[mt][np * 2 + 1], af[mt], bf[2], bf[3]);
                    }
                }
            }
        }

        // Epilogue (overlaps next tile's in-flight prologue loads)
#pragma unroll
        for (int mt = 0; mt < 4; mt++) {
#pragma unroll
            for (int nt = 0; nt < 8; nt++) {
                const int row = m0 + wm * 64 + mt * 16 + (lane >> 2);
                const int col = n0 + wn * 64 + nt * 8 + (lane & 3) * 2;
                const float b0 = bias[col], b1 = bias[col + 1];
                float2 v0 = {acc[mt][nt][0] + b0, acc[mt][nt][1] + b1};
                float2 v1 = {acc[mt][nt][2] + b0, acc[mt][nt][3] + b1};
                __stcs((float2*)(out + (size_t)row * O_DIM + col), v0);
                __stcs((float2*)(out + (size_t)(row + 8) * O_DIM + col), v1);
            }
        }

        if (!hasn) break;
        tile = ntile; m0 = mn0; n0 = nn0; aQ = aN; bQ = bN;
    }
#undef LOAD_ST
}

// ---------------------------------------------------------------------------
extern "C" void kernel_launch(void* const* d_in, const int* in_sizes, int n_in,
                              void* d_out, int out_size) {
    const int*   qweight   = (const int*)d_in[0];
    const float* scales    = (const float*)d_in[1];
    const float* lora_up   = (const float*)d_in[2];
    const float* lora_down = (const float*)d_in[3];
    const float* bias      = (const float*)d_in[4];
    const float* x         = (const float*)d_in[5];
    float* out = (float*)d_out;

    prep_fused<<<O_DIM + XBLK, 256>>>(qweight, scales, lora_up, lora_down, x);

    int dev = 0, nsm = 148;
    cudaGetDevice(&dev);
    cudaDeviceGetAttribute(&nsm, cudaDevAttrMultiProcessorCount, dev);

    cudaFuncSetAttribute(gemm_fp16,
                         cudaFuncAttributeMaxDynamicSharedMemorySize, SMEM_BYTES);
    gemm_fp16<<<2 * nsm, NTHREADS, SMEM_BYTES>>>(bias, out);
}